// round 2
// baseline (speedup 1.0000x reference)
#include <cuda_runtime.h>
#include <math.h>

#define Nn 8192
#define Dd 64
#define NCHUNK 64              // row chunks in v-pass
#define VROWS (Nn / NCHUNK)    // 128 rows per chunk
#define VCOLS 512              // cols per tile (128 threads * 4)
#define NTILE (Nn / VCOLS)     // 16

// -ln(8192) = -13*ln(2)
#define LOG_AB (-9.010913347f)

// ---------------- device scratch (static: no allocations allowed) ----------
__device__ float d_C[(size_t)Nn * Nn];     // cost matrix, 268 MB
__device__ float d_x2[Nn], d_y2[Nn];
__device__ float d_u[Nn], d_v[Nn];
__device__ float d_spart[NCHUNK][Nn];      // v-pass partial sums
__device__ float d_Tpart[NCHUNK][Nn];      // final-pass partial C-weighted sums
__device__ float d_rj[Nn];
__device__ unsigned int d_cmax_bits;
__device__ float d_negS;                   // -1/(reg * Cmax)

// ---------------- row norms -------------------------------------------------
__global__ void norms_kernel(const float* __restrict__ XP,
                             const float* __restrict__ XQ) {
    int gwarp = (blockIdx.x * blockDim.x + threadIdx.x) >> 5;
    int lane = threadIdx.x & 31;
    const float* src;
    float* dst;
    int row;
    if (gwarp < Nn) { src = XP; dst = d_x2; row = gwarp; }
    else            { src = XQ; dst = d_y2; row = gwarp - Nn; }
    const float* r = src + (size_t)row * Dd;
    float a = r[lane];
    float b = r[lane + 32];
    float s = a * a + b * b;
    #pragma unroll
    for (int o = 16; o; o >>= 1) s += __shfl_xor_sync(0xffffffffu, s, o);
    if (lane == 0) dst[row] = s;
}

// ---------------- init (u=v=0, cmax=0) -------------------------------------
__global__ void init_kernel() {
    int j = blockIdx.x * blockDim.x + threadIdx.x;
    d_u[j] = 0.0f;
    d_v[j] = 0.0f;
    if (j == 0) d_cmax_bits = 0u;
}

// ---------------- C = max(x2 + y2 - 2 XP@XQ^T, 0), track max ---------------
__global__ void gemmC_kernel(const float* __restrict__ XP,
                             const float* __restrict__ XQ) {
    __shared__ float As[Dd][64 + 4];   // [k][m], pad=4 keeps float4 alignment
    __shared__ float Bs[Dd][64 + 4];   // [k][n]
    int tid = threadIdx.x;             // 256 threads
    int m0 = blockIdx.y * 64;
    int n0 = blockIdx.x * 64;

    #pragma unroll
    for (int p = 0; p < 4; ++p) {
        int f = p * 256 + tid;         // float4 id 0..1023
        int row = f >> 4;              // 0..63
        int c4 = f & 15;               // 0..15
        float4 a = *(const float4*)(XP + (size_t)(m0 + row) * Dd + c4 * 4);
        As[c4 * 4 + 0][row] = a.x; As[c4 * 4 + 1][row] = a.y;
        As[c4 * 4 + 2][row] = a.z; As[c4 * 4 + 3][row] = a.w;
        float4 b = *(const float4*)(XQ + (size_t)(n0 + row) * Dd + c4 * 4);
        Bs[c4 * 4 + 0][row] = b.x; Bs[c4 * 4 + 1][row] = b.y;
        Bs[c4 * 4 + 2][row] = b.z; Bs[c4 * 4 + 3][row] = b.w;
    }
    __syncthreads();

    int tx = tid & 15, ty = tid >> 4;
    float acc[4][4] = {};
    #pragma unroll
    for (int k = 0; k < Dd; ++k) {
        float4 a4 = *(const float4*)&As[k][ty * 4];
        float4 b4 = *(const float4*)&Bs[k][tx * 4];
        float a[4] = {a4.x, a4.y, a4.z, a4.w};
        float b[4] = {b4.x, b4.y, b4.z, b4.w};
        #pragma unroll
        for (int i = 0; i < 4; ++i)
            #pragma unroll
            for (int j = 0; j < 4; ++j)
                acc[i][j] = fmaf(a[i], b[j], acc[i][j]);
    }

    float cmaxl = 0.0f;
    #pragma unroll
    for (int i = 0; i < 4; ++i) {
        int m = m0 + ty * 4 + i;
        float xm = d_x2[m];
        float4 out;
        float* o = &out.x;
        #pragma unroll
        for (int j = 0; j < 4; ++j) {
            int nj = n0 + tx * 4 + j;
            float c = fmaxf(xm + d_y2[nj] - 2.0f * acc[i][j], 0.0f);
            o[j] = c;
            cmaxl = fmaxf(cmaxl, c);
        }
        *(float4*)(d_C + (size_t)m * Nn + n0 + tx * 4) = out;
    }
    #pragma unroll
    for (int o = 16; o; o >>= 1)
        cmaxl = fmaxf(cmaxl, __shfl_xor_sync(0xffffffffu, cmaxl, o));
    if ((tid & 31) == 0)
        atomicMax(&d_cmax_bits, __float_as_uint(cmaxl));  // >=0 floats: bit order == value order
}

__global__ void scale_kernel() {
    float cmax = __uint_as_float(d_cmax_bits);
    d_negS = -1.0f / (0.05f * cmax);
}

// ---------------- u-pass: u_new = u_prev - ln sum_j exp(M + v + u_prev - log_a)
__global__ void upass_kernel() {
    __shared__ float vs[Nn];           // 32 KB
    int tid = threadIdx.x;             // 256
    #pragma unroll
    for (int p = 0; p < Nn / 256 / 4; ++p) {
        int f = p * 256 + tid;
        *(float4*)&vs[f * 4] = *(const float4*)&d_v[f * 4];
    }
    __syncthreads();

    float negS = d_negS;
    int warp = tid >> 5, lane = tid & 31;
    int row = blockIdx.x * 8 + warp;
    float up = d_u[row];
    float roff = up - LOG_AB;          // shift folded in
    const float* Crow = d_C + (size_t)row * Nn;

    float s0 = 0.f, s1 = 0.f, s2 = 0.f, s3 = 0.f;
    #pragma unroll 4
    for (int it = 0; it < Nn / 128; ++it) {
        int j = it * 128 + lane * 4;
        float4 c = *(const float4*)(Crow + j);
        float4 v4 = *(const float4*)&vs[j];
        s0 += __expf(fmaf(c.x, negS, v4.x + roff));
        s1 += __expf(fmaf(c.y, negS, v4.y + roff));
        s2 += __expf(fmaf(c.z, negS, v4.z + roff));
        s3 += __expf(fmaf(c.w, negS, v4.w + roff));
    }
    float s = (s0 + s1) + (s2 + s3);
    #pragma unroll
    for (int o = 16; o; o >>= 1) s += __shfl_xor_sync(0xffffffffu, s, o);
    if (lane == 0) d_u[row] = up - __logf(s);
}

// ---------------- v-pass: partial col sums exp(M + u + v_prev - log_b) -----
template <bool FINAL>
__global__ void vpass_kernel() {
    __shared__ float us[VROWS];
    int tid = threadIdx.x;             // 128
    int tile = blockIdx.x;             // 0..15
    int chunk = blockIdx.y;            // 0..63
    int i0 = chunk * VROWS;
    us[tid] = d_u[i0 + tid];
    __syncthreads();

    float negS = d_negS;
    int j = tile * VCOLS + tid * 4;
    float4 vp = *(const float4*)&d_v[j];
    float dd0 = vp.x - LOG_AB, dd1 = vp.y - LOG_AB;
    float dd2 = vp.z - LOG_AB, dd3 = vp.w - LOG_AB;

    float s0 = 0.f, s1 = 0.f, s2 = 0.f, s3 = 0.f;
    float t0 = 0.f, t1 = 0.f, t2 = 0.f, t3 = 0.f;
    const float* Cp = d_C + (size_t)i0 * Nn + j;

    #pragma unroll 4
    for (int i = 0; i < VROWS; ++i) {
        float ui = us[i];
        float4 c = *(const float4*)(Cp + (size_t)i * Nn);
        float e0 = __expf(fmaf(c.x, negS, ui + dd0));
        float e1 = __expf(fmaf(c.y, negS, ui + dd1));
        float e2 = __expf(fmaf(c.z, negS, ui + dd2));
        float e3 = __expf(fmaf(c.w, negS, ui + dd3));
        s0 += e0; s1 += e1; s2 += e2; s3 += e3;
        if (FINAL) {
            t0 = fmaf(c.x, e0, t0); t1 = fmaf(c.y, e1, t1);
            t2 = fmaf(c.z, e2, t2); t3 = fmaf(c.w, e3, t3);
        }
    }
    *(float4*)&d_spart[chunk][j] = make_float4(s0, s1, s2, s3);
    if (FINAL)
        *(float4*)&d_Tpart[chunk][j] = make_float4(t0, t1, t2, t3);
}

// deterministic fixed-order merge of v partials
__global__ void vfinalize_kernel() {
    int j = blockIdx.x * blockDim.x + threadIdx.x;
    float s = 0.f;
    #pragma unroll
    for (int c = 0; c < NCHUNK; ++c) s += d_spart[c][j];
    d_v[j] = d_v[j] - __logf(s);
}

// final contribution per column: r_j = T_j / s_j  (result = (1/m) sum_j r_j)
__global__ void rj_kernel() {
    int j = blockIdx.x * blockDim.x + threadIdx.x;
    float s = 0.f, t = 0.f;
    #pragma unroll
    for (int c = 0; c < NCHUNK; ++c) { s += d_spart[c][j]; t += d_Tpart[c][j]; }
    d_rj[j] = t / s;
}

__global__ void result_kernel(float* __restrict__ out) {
    __shared__ float red[256];
    int tid = threadIdx.x;
    float s = 0.f;
    for (int j = tid; j < Nn; j += 256) s += d_rj[j];
    red[tid] = s;
    __syncthreads();
    for (int o = 128; o; o >>= 1) {
        if (tid < o) red[tid] += red[tid + o];
        __syncthreads();
    }
    if (tid == 0) out[0] = red[0] * (1.0f / Nn);
}

// ---------------------------------------------------------------------------
extern "C" void kernel_launch(void* const* d_in, const int* in_sizes, int n_in,
                              void* d_out, int out_size) {
    const float* XP = (const float*)d_in[0];
    const float* XQ = (const float*)d_in[1];
    float* out = (float*)d_out;

    norms_kernel<<<(2 * Nn) / 8, 256>>>(XP, XQ);
    init_kernel<<<Nn / 256, 256>>>();
    gemmC_kernel<<<dim3(Nn / 64, Nn / 64), 256>>>(XP, XQ);
    scale_kernel<<<1, 1>>>();

    for (int t = 0; t < 20; ++t) {
        upass_kernel<<<Nn / 8, 256>>>();
        if (t < 19) {
            vpass_kernel<false><<<dim3(NTILE, NCHUNK), 128>>>();
            vfinalize_kernel<<<Nn / 256, 256>>>();
        } else {
            vpass_kernel<true><<<dim3(NTILE, NCHUNK), 128>>>();
            rj_kernel<<<Nn / 256, 256>>>();
            result_kernel<<<1, 256>>>(out);
        }
    }
}

// round 4
// speedup vs baseline: 1.2387x; 1.2387x over previous
#include <cuda_runtime.h>
#include <cuda_fp16.h>
#include <math.h>

#define Nn 8192
#define Dd 64
#define NCHUNK 64              // row chunks in v-pass
#define VROWS (Nn / NCHUNK)    // 128 rows per chunk
#define VCOLS 1024             // cols per tile (128 threads * 8)
#define NTILE (Nn / VCOLS)     // 8

// -ln(8192) = -13*ln(2)
#define LOG_AB (-9.010913347f)

// ---------------- device scratch (static: no allocations allowed) ----------
__device__ __half d_C[(size_t)Nn * Nn];    // cost matrix, fp16, 134 MB
__device__ float d_x2[Nn], d_y2[Nn];
__device__ float d_u[Nn], d_v[Nn];
__device__ float d_spart[NCHUNK][Nn];      // v-pass partial sums
__device__ float d_Tpart[NCHUNK][Nn];      // final-pass partial C-weighted sums
__device__ float d_rj[Nn];
__device__ unsigned int d_cmax_bits;
__device__ float d_negS;                   // -1/(reg * Cmax)

// ---------------- row norms -------------------------------------------------
__global__ void norms_kernel(const float* __restrict__ XP,
                             const float* __restrict__ XQ) {
    int gwarp = (blockIdx.x * blockDim.x + threadIdx.x) >> 5;
    int lane = threadIdx.x & 31;
    const float* src;
    float* dst;
    int row;
    if (gwarp < Nn) { src = XP; dst = d_x2; row = gwarp; }
    else            { src = XQ; dst = d_y2; row = gwarp - Nn; }
    const float* r = src + (size_t)row * Dd;
    float a = r[lane];
    float b = r[lane + 32];
    float s = a * a + b * b;
    #pragma unroll
    for (int o = 16; o; o >>= 1) s += __shfl_xor_sync(0xffffffffu, s, o);
    if (lane == 0) dst[row] = s;
}

// ---------------- init (u=v=0, cmax=0) -------------------------------------
__global__ void init_kernel() {
    int j = blockIdx.x * blockDim.x + threadIdx.x;
    d_u[j] = 0.0f;
    d_v[j] = 0.0f;
    if (j == 0) d_cmax_bits = 0u;
}

// ---------------- C = max(x2 + y2 - 2 XP@XQ^T, 0) -> fp16, track fp32 max --
__global__ void gemmC_kernel(const float* __restrict__ XP,
                             const float* __restrict__ XQ) {
    __shared__ float As[Dd][64 + 4];   // [k][m]
    __shared__ float Bs[Dd][64 + 4];   // [k][n]
    int tid = threadIdx.x;             // 256 threads
    int m0 = blockIdx.y * 64;
    int n0 = blockIdx.x * 64;

    #pragma unroll
    for (int p = 0; p < 4; ++p) {
        int f = p * 256 + tid;         // float4 id 0..1023
        int row = f >> 4;              // 0..63
        int c4 = f & 15;               // 0..15
        float4 a = *(const float4*)(XP + (size_t)(m0 + row) * Dd + c4 * 4);
        As[c4 * 4 + 0][row] = a.x; As[c4 * 4 + 1][row] = a.y;
        As[c4 * 4 + 2][row] = a.z; As[c4 * 4 + 3][row] = a.w;
        float4 b = *(const float4*)(XQ + (size_t)(n0 + row) * Dd + c4 * 4);
        Bs[c4 * 4 + 0][row] = b.x; Bs[c4 * 4 + 1][row] = b.y;
        Bs[c4 * 4 + 2][row] = b.z; Bs[c4 * 4 + 3][row] = b.w;
    }
    __syncthreads();

    int tx = tid & 15, ty = tid >> 4;
    float acc[4][4] = {};
    #pragma unroll
    for (int k = 0; k < Dd; ++k) {
        float4 a4 = *(const float4*)&As[k][ty * 4];
        float4 b4 = *(const float4*)&Bs[k][tx * 4];
        float a[4] = {a4.x, a4.y, a4.z, a4.w};
        float b[4] = {b4.x, b4.y, b4.z, b4.w};
        #pragma unroll
        for (int i = 0; i < 4; ++i)
            #pragma unroll
            for (int j = 0; j < 4; ++j)
                acc[i][j] = fmaf(a[i], b[j], acc[i][j]);
    }

    float cmaxl = 0.0f;
    #pragma unroll
    for (int i = 0; i < 4; ++i) {
        int m = m0 + ty * 4 + i;
        float xm = d_x2[m];
        float o[4];
        #pragma unroll
        for (int j = 0; j < 4; ++j) {
            int nj = n0 + tx * 4 + j;
            float c = fmaxf(xm + d_y2[nj] - 2.0f * acc[i][j], 0.0f);
            o[j] = c;
            cmaxl = fmaxf(cmaxl, c);
        }
        __half2* dst = (__half2*)(d_C + (size_t)m * Nn + n0 + tx * 4);
        dst[0] = __floats2half2_rn(o[0], o[1]);
        dst[1] = __floats2half2_rn(o[2], o[3]);
    }
    #pragma unroll
    for (int o = 16; o; o >>= 1)
        cmaxl = fmaxf(cmaxl, __shfl_xor_sync(0xffffffffu, cmaxl, o));
    if ((tid & 31) == 0)
        atomicMax(&d_cmax_bits, __float_as_uint(cmaxl));  // >=0 floats: bit order == value order
}

__global__ void scale_kernel() {
    float cmax = __uint_as_float(d_cmax_bits);
    d_negS = -1.0f / (0.05f * cmax);
}

// ---------------- u-pass: u_new = u_prev - ln sum_j exp(M + v + u_prev - log_a)
__global__ void upass_kernel() {
    __shared__ float vs[Nn];           // 32 KB
    int tid = threadIdx.x;             // 256
    #pragma unroll
    for (int p = 0; p < Nn / 256 / 4; ++p) {
        int f = p * 256 + tid;
        *(float4*)&vs[f * 4] = *(const float4*)&d_v[f * 4];
    }
    __syncthreads();

    float negS = d_negS;
    int warp = tid >> 5, lane = tid & 31;
    int row = blockIdx.x * 8 + warp;
    float up = d_u[row];
    float roff = up - LOG_AB;          // shift folded in
    const __half* Crow = d_C + (size_t)row * Nn;

    float s0 = 0.f, s1 = 0.f, s2 = 0.f, s3 = 0.f;
    #pragma unroll 4
    for (int it = 0; it < Nn / 256; ++it) {
        int j = it * 256 + lane * 8;
        uint4 raw = *(const uint4*)(Crow + j);
        const __half2* hp = (const __half2*)&raw;
        float2 c01 = __half22float2(hp[0]);
        float2 c23 = __half22float2(hp[1]);
        float2 c45 = __half22float2(hp[2]);
        float2 c67 = __half22float2(hp[3]);
        float4 va = *(const float4*)&vs[j];
        float4 vb = *(const float4*)&vs[j + 4];
        s0 += __expf(fmaf(c01.x, negS, va.x + roff));
        s1 += __expf(fmaf(c01.y, negS, va.y + roff));
        s2 += __expf(fmaf(c23.x, negS, va.z + roff));
        s3 += __expf(fmaf(c23.y, negS, va.w + roff));
        s0 += __expf(fmaf(c45.x, negS, vb.x + roff));
        s1 += __expf(fmaf(c45.y, negS, vb.y + roff));
        s2 += __expf(fmaf(c67.x, negS, vb.z + roff));
        s3 += __expf(fmaf(c67.y, negS, vb.w + roff));
    }
    float s = (s0 + s1) + (s2 + s3);
    #pragma unroll
    for (int o = 16; o; o >>= 1) s += __shfl_xor_sync(0xffffffffu, s, o);
    if (lane == 0) d_u[row] = up - __logf(s);
}

// ---------------- v-pass: partial col sums exp(M + u + v_prev - log_b) -----
template <bool FINAL>
__global__ void vpass_kernel() {
    __shared__ float us[VROWS];
    int tid = threadIdx.x;             // 128
    int tile = blockIdx.x;             // 0..NTILE-1
    int chunk = blockIdx.y;            // 0..63
    int i0 = chunk * VROWS;
    us[tid] = d_u[i0 + tid];
    __syncthreads();

    float negS = d_negS;
    int j = tile * VCOLS + tid * 8;
    float4 va = *(const float4*)&d_v[j];
    float4 vb = *(const float4*)&d_v[j + 4];
    float dd[8] = {va.x - LOG_AB, va.y - LOG_AB, va.z - LOG_AB, va.w - LOG_AB,
                   vb.x - LOG_AB, vb.y - LOG_AB, vb.z - LOG_AB, vb.w - LOG_AB};

    float s[8] = {};
    float t[8] = {};
    const __half* Cp = d_C + (size_t)i0 * Nn + j;

    #pragma unroll 4
    for (int i = 0; i < VROWS; ++i) {
        float ui = us[i];
        uint4 raw = *(const uint4*)(Cp + (size_t)i * Nn);
        const __half2* hp = (const __half2*)&raw;
        float c[8];
        float2 f;
        f = __half22float2(hp[0]); c[0] = f.x; c[1] = f.y;
        f = __half22float2(hp[1]); c[2] = f.x; c[3] = f.y;
        f = __half22float2(hp[2]); c[4] = f.x; c[5] = f.y;
        f = __half22float2(hp[3]); c[6] = f.x; c[7] = f.y;
        #pragma unroll
        for (int q = 0; q < 8; ++q) {
            float e = __expf(fmaf(c[q], negS, ui + dd[q]));
            s[q] += e;
            if (FINAL) t[q] = fmaf(c[q], e, t[q]);
        }
    }
    *(float4*)&d_spart[chunk][j]     = make_float4(s[0], s[1], s[2], s[3]);
    *(float4*)&d_spart[chunk][j + 4] = make_float4(s[4], s[5], s[6], s[7]);
    if (FINAL) {
        *(float4*)&d_Tpart[chunk][j]     = make_float4(t[0], t[1], t[2], t[3]);
        *(float4*)&d_Tpart[chunk][j + 4] = make_float4(t[4], t[5], t[6], t[7]);
    }
}

// deterministic fixed-order merge of v partials
__global__ void vfinalize_kernel() {
    int j = blockIdx.x * blockDim.x + threadIdx.x;
    float s = 0.f;
    #pragma unroll
    for (int c = 0; c < NCHUNK; ++c) s += d_spart[c][j];
    d_v[j] = d_v[j] - __logf(s);
}

// final contribution per column: r_j = T_j / s_j  (result = (1/m) sum_j r_j)
__global__ void rj_kernel() {
    int j = blockIdx.x * blockDim.x + threadIdx.x;
    float s = 0.f, t = 0.f;
    #pragma unroll
    for (int c = 0; c < NCHUNK; ++c) { s += d_spart[c][j]; t += d_Tpart[c][j]; }
    d_rj[j] = t / s;
}

__global__ void result_kernel(float* __restrict__ out) {
    __shared__ float red[256];
    int tid = threadIdx.x;
    float s = 0.f;
    for (int j = tid; j < Nn; j += 256) s += d_rj[j];
    red[tid] = s;
    __syncthreads();
    for (int o = 128; o; o >>= 1) {
        if (tid < o) red[tid] += red[tid + o];
        __syncthreads();
    }
    if (tid == 0) out[0] = red[0] * (1.0f / Nn);
}

// ---------------------------------------------------------------------------
extern "C" void kernel_launch(void* const* d_in, const int* in_sizes, int n_in,
                              void* d_out, int out_size) {
    const float* XP = (const float*)d_in[0];
    const float* XQ = (const float*)d_in[1];
    float* out = (float*)d_out;

    norms_kernel<<<(2 * Nn) / 8, 256>>>(XP, XQ);
    init_kernel<<<Nn / 256, 256>>>();
    gemmC_kernel<<<dim3(Nn / 64, Nn / 64), 256>>>(XP, XQ);
    scale_kernel<<<1, 1>>>();

    for (int t = 0; t < 20; ++t) {
        upass_kernel<<<Nn / 8, 256>>>();
        if (t < 19) {
            vpass_kernel<false><<<dim3(NTILE, NCHUNK), 128>>>();
            vfinalize_kernel<<<Nn / 256, 256>>>();
        } else {
            vpass_kernel<true><<<dim3(NTILE, NCHUNK), 128>>>();
            rj_kernel<<<Nn / 256, 256>>>();
            result_kernel<<<1, 256>>>(out);
        }
    }
}

// round 8
// speedup vs baseline: 2.4421x; 1.9715x over previous
#include <cuda_runtime.h>
#include <cuda_fp16.h>
#include <math.h>

#define Nn 8192
#define Dd 64
#define NCHUNK 128             // row chunks in v-pass
#define VROWS (Nn / NCHUNK)    // 64 rows per chunk
#define VCOLS 1024             // cols per tile (128 threads * 8)
#define NTILE (Nn / VCOLS)     // 8

#define LOG_AB (-9.010913347f)   // -ln(8192)
#define LOG2E  (1.4426950408889634f)
#define LN2    (0.6931471805599453f)
#define BIAS   (12.0f)

// ---------------- device scratch ----------
__device__ __half d_C[(size_t)Nn * Nn];    // C (fp16) then rescaled a' = C*alpha+12
__device__ float d_x2[Nn], d_y2[Nn];
__device__ float d_u[Nn], d_v[Nn];
__device__ float d_spart[NCHUNK][Nn];
__device__ float d_Tpart[NCHUNK][Nn];
__device__ float d_rj[Nn];
__device__ unsigned int d_cmax_bits;
__device__ float d_alpha;                  // negS*LOG2E  (negative)
__device__ float d_invAlpha;               // 1/alpha

__device__ __forceinline__ __half2 h2exp2_fast(__half2 x) {
    unsigned xi = *reinterpret_cast<unsigned*>(&x);
    unsigned ri;
    asm("ex2.approx.f16x2 %0, %1;" : "=r"(ri) : "r"(xi));
    return *reinterpret_cast<__half2*>(&ri);
}

// ---------------- row norms ----------------
__global__ void norms_kernel(const float* __restrict__ XP,
                             const float* __restrict__ XQ) {
    int gwarp = (blockIdx.x * blockDim.x + threadIdx.x) >> 5;
    int lane = threadIdx.x & 31;
    const float* src;
    float* dst;
    int row;
    if (gwarp < Nn) { src = XP; dst = d_x2; row = gwarp; }
    else            { src = XQ; dst = d_y2; row = gwarp - Nn; }
    const float* r = src + (size_t)row * Dd;
    float a = r[lane];
    float b = r[lane + 32];
    float s = a * a + b * b;
    #pragma unroll
    for (int o = 16; o; o >>= 1) s += __shfl_xor_sync(0xffffffffu, s, o);
    if (lane == 0) dst[row] = s;
}

__global__ void init_kernel() {
    int j = blockIdx.x * blockDim.x + threadIdx.x;
    d_u[j] = 0.0f;
    d_v[j] = 0.0f;
    if (j == 0) d_cmax_bits = 0u;
}

// ---------------- C = max(x2 + y2 - 2 XP@XQ^T, 0) -> fp16, track fp32 max --
__global__ void gemmC_kernel(const float* __restrict__ XP,
                             const float* __restrict__ XQ) {
    __shared__ float As[Dd][64 + 4];
    __shared__ float Bs[Dd][64 + 4];
    int tid = threadIdx.x;             // 256 threads
    int m0 = blockIdx.y * 64;
    int n0 = blockIdx.x * 64;

    #pragma unroll
    for (int p = 0; p < 4; ++p) {
        int f = p * 256 + tid;
        int row = f >> 4;
        int c4 = f & 15;
        float4 a = *(const float4*)(XP + (size_t)(m0 + row) * Dd + c4 * 4);
        As[c4 * 4 + 0][row] = a.x; As[c4 * 4 + 1][row] = a.y;
        As[c4 * 4 + 2][row] = a.z; As[c4 * 4 + 3][row] = a.w;
        float4 b = *(const float4*)(XQ + (size_t)(n0 + row) * Dd + c4 * 4);
        Bs[c4 * 4 + 0][row] = b.x; Bs[c4 * 4 + 1][row] = b.y;
        Bs[c4 * 4 + 2][row] = b.z; Bs[c4 * 4 + 3][row] = b.w;
    }
    __syncthreads();

    int tx = tid & 15, ty = tid >> 4;
    float acc[4][4] = {};
    #pragma unroll
    for (int k = 0; k < Dd; ++k) {
        float4 a4 = *(const float4*)&As[k][ty * 4];
        float4 b4 = *(const float4*)&Bs[k][tx * 4];
        float a[4] = {a4.x, a4.y, a4.z, a4.w};
        float b[4] = {b4.x, b4.y, b4.z, b4.w};
        #pragma unroll
        for (int i = 0; i < 4; ++i)
            #pragma unroll
            for (int j = 0; j < 4; ++j)
                acc[i][j] = fmaf(a[i], b[j], acc[i][j]);
    }

    float cmaxl = 0.0f;
    #pragma unroll
    for (int i = 0; i < 4; ++i) {
        int m = m0 + ty * 4 + i;
        float xm = d_x2[m];
        float o[4];
        #pragma unroll
        for (int j = 0; j < 4; ++j) {
            int nj = n0 + tx * 4 + j;
            float c = fmaxf(xm + d_y2[nj] - 2.0f * acc[i][j], 0.0f);
            o[j] = c;
            cmaxl = fmaxf(cmaxl, c);
        }
        __half2* dst = (__half2*)(d_C + (size_t)m * Nn + n0 + tx * 4);
        dst[0] = __floats2half2_rn(o[0], o[1]);
        dst[1] = __floats2half2_rn(o[2], o[3]);
    }
    #pragma unroll
    for (int o = 16; o; o >>= 1)
        cmaxl = fmaxf(cmaxl, __shfl_xor_sync(0xffffffffu, cmaxl, o));
    if ((tid & 31) == 0)
        atomicMax(&d_cmax_bits, __float_as_uint(cmaxl));  // nonneg floats: bit order == value order
}

__global__ void scale_kernel() {
    float cmax = __uint_as_float(d_cmax_bits);
    float negS = -1.0f / (0.05f * cmax);
    float alpha = negS * LOG2E;
    d_alpha = alpha;
    d_invAlpha = 1.0f / alpha;
}

// a' = C*alpha + 12, in place (fp16)
__global__ void rescale_kernel() {
    float alpha = d_alpha;
    size_t idx = ((size_t)blockIdx.x * 256 + threadIdx.x) * 8;
    uint4 raw = *(uint4*)(d_C + idx);
    __half2* hp = (__half2*)&raw;
    #pragma unroll
    for (int k = 0; k < 4; ++k) {
        float2 f = __half22float2(hp[k]);
        hp[k] = __floats2half2_rn(fmaf(f.x, alpha, BIAS), fmaf(f.y, alpha, BIAS));
    }
    *(uint4*)(d_C + idx) = raw;
}

// ---------------- u-pass: u_new = up - rc*ln2 - ln( sum_j 2^(a' + v_j*log2e) )
__global__ void upass_kernel() {
    __shared__ __half2 vs2[Nn / 2];    // 8 KB: v_j*LOG2E as half2
    int tid = threadIdx.x;             // 256
    #pragma unroll
    for (int p = 0; p < 8; ++p) {
        int idx = p * 256 + tid;       // float4 index
        float4 f = *(const float4*)&d_v[idx * 4];
        vs2[idx * 2]     = __floats2half2_rn(f.x * LOG2E, f.y * LOG2E);
        vs2[idx * 2 + 1] = __floats2half2_rn(f.z * LOG2E, f.w * LOG2E);
    }
    __syncthreads();

    int warp = tid >> 5, lane = tid & 31;
    int row = blockIdx.x * 8 + warp;
    float up = d_u[row];
    const __half* Crow = d_C + (size_t)row * Nn;

    float2 f0 = make_float2(0.f, 0.f), f1 = f0, f2 = f0, f3 = f0;
    #pragma unroll
    for (int blk = 0; blk < 4; ++blk) {
        __half2 h0 = __float2half2_rn(0.f), h1 = h0, h2 = h0, h3 = h0;
        #pragma unroll
        for (int it = 0; it < 8; ++it) {
            int j = (blk * 8 + it) * 256 + lane * 8;
            uint4 raw = *(const uint4*)(Crow + j);
            uint4 vr = *(const uint4*)&vs2[j >> 1];
            const __half2* a = (const __half2*)&raw;
            const __half2* v = (const __half2*)&vr;
            h0 = __hadd2(h0, h2exp2_fast(__hadd2(a[0], v[0])));
            h1 = __hadd2(h1, h2exp2_fast(__hadd2(a[1], v[1])));
            h2 = __hadd2(h2, h2exp2_fast(__hadd2(a[2], v[2])));
            h3 = __hadd2(h3, h2exp2_fast(__hadd2(a[3], v[3])));
        }
        float2 g;
        g = __half22float2(h0); f0.x += g.x; f0.y += g.y;
        g = __half22float2(h1); f1.x += g.x; f1.y += g.y;
        g = __half22float2(h2); f2.x += g.x; f2.y += g.y;
        g = __half22float2(h3); f3.x += g.x; f3.y += g.y;
    }
    float s = ((f0.x + f0.y) + (f1.x + f1.y)) + ((f2.x + f2.y) + (f3.x + f3.y));
    #pragma unroll
    for (int o = 16; o; o >>= 1) s += __shfl_xor_sync(0xffffffffu, s, o);
    if (lane == 0) {
        float rc = (up - LOG_AB) * LOG2E - BIAS;
        d_u[row] = up - rc * LN2 - __logf(s);
    }
}

// ---------------- v-pass: partial col sums of 2^(a' + u_i*log2e) -----------
template <bool FINAL>
__global__ void vpass_kernel() {
    __shared__ __half2 us2[VROWS];     // u_i*LOG2E duplicated in both halves
    int tid = threadIdx.x;             // 128
    int tile = blockIdx.x;             // 0..NTILE-1
    int chunk = blockIdx.y;            // 0..NCHUNK-1
    int i0 = chunk * VROWS;
    if (tid < VROWS)
        us2[tid] = __float2half2_rn(d_u[i0 + tid] * LOG2E);
    __syncthreads();

    int j = tile * VCOLS + tid * 8;
    const __half* Cp = d_C + (size_t)i0 * Nn + j;

    float2 f0 = make_float2(0.f, 0.f), f1 = f0, f2 = f0, f3 = f0;
    float2 t0 = f0, t1 = f0, t2 = f0, t3 = f0;

    #pragma unroll
    for (int blk = 0; blk < VROWS / 8; ++blk) {
        __half2 h0 = __float2half2_rn(0.f), h1 = h0, h2 = h0, h3 = h0;
        #pragma unroll
        for (int it = 0; it < 8; ++it) {
            int i = blk * 8 + it;
            __half2 ui = us2[i];
            uint4 raw = *(const uint4*)(Cp + (size_t)i * Nn);
            const __half2* a = (const __half2*)&raw;
            __half2 e0 = h2exp2_fast(__hadd2(a[0], ui));
            __half2 e1 = h2exp2_fast(__hadd2(a[1], ui));
            __half2 e2 = h2exp2_fast(__hadd2(a[2], ui));
            __half2 e3 = h2exp2_fast(__hadd2(a[3], ui));
            h0 = __hadd2(h0, e0); h1 = __hadd2(h1, e1);
            h2 = __hadd2(h2, e2); h3 = __hadd2(h3, e3);
            if (FINAL) {
                float2 af, ef;
                af = __half22float2(a[0]); ef = __half22float2(e0);
                t0.x = fmaf(af.x, ef.x, t0.x); t0.y = fmaf(af.y, ef.y, t0.y);
                af = __half22float2(a[1]); ef = __half22float2(e1);
                t1.x = fmaf(af.x, ef.x, t1.x); t1.y = fmaf(af.y, ef.y, t1.y);
                af = __half22float2(a[2]); ef = __half22float2(e2);
                t2.x = fmaf(af.x, ef.x, t2.x); t2.y = fmaf(af.y, ef.y, t2.y);
                af = __half22float2(a[3]); ef = __half22float2(e3);
                t3.x = fmaf(af.x, ef.x, t3.x); t3.y = fmaf(af.y, ef.y, t3.y);
            }
        }
        float2 g;
        g = __half22float2(h0); f0.x += g.x; f0.y += g.y;
        g = __half22float2(h1); f1.x += g.x; f1.y += g.y;
        g = __half22float2(h2); f2.x += g.x; f2.y += g.y;
        g = __half22float2(h3); f3.x += g.x; f3.y += g.y;
    }
    *(float4*)&d_spart[chunk][j]     = make_float4(f0.x, f0.y, f1.x, f1.y);
    *(float4*)&d_spart[chunk][j + 4] = make_float4(f2.x, f2.y, f3.x, f3.y);
    if (FINAL) {
        *(float4*)&d_Tpart[chunk][j]     = make_float4(t0.x, t0.y, t1.x, t1.y);
        *(float4*)&d_Tpart[chunk][j + 4] = make_float4(t2.x, t2.y, t3.x, t3.y);
    }
}

// deterministic fixed-order merge of v partials
__global__ void vfinalize_kernel() {
    int j = blockIdx.x * blockDim.x + threadIdx.x;
    float s = 0.f;
    #pragma unroll
    for (int c = 0; c < NCHUNK; ++c) s += d_spart[c][j];
    float vp = d_v[j];
    float cc = (vp - LOG_AB) * LOG2E - BIAS;
    d_v[j] = vp - cc * LN2 - __logf(s);
}

// r_j = T_j/s_j in C units: ((sum a'e / sum e) - 12) / alpha
__global__ void rj_kernel() {
    int j = blockIdx.x * blockDim.x + threadIdx.x;
    float s = 0.f, t = 0.f;
    #pragma unroll
    for (int c = 0; c < NCHUNK; ++c) { s += d_spart[c][j]; t += d_Tpart[c][j]; }
    d_rj[j] = (t / s - BIAS) * d_invAlpha;
}

__global__ void result_kernel(float* __restrict__ out) {
    __shared__ float red[256];
    int tid = threadIdx.x;
    float s = 0.f;
    for (int j = tid; j < Nn; j += 256) s += d_rj[j];
    red[tid] = s;
    __syncthreads();
    for (int o = 128; o; o >>= 1) {
        if (tid < o) red[tid] += red[tid + o];
        __syncthreads();
    }
    if (tid == 0) out[0] = red[0] * (1.0f / Nn);
}

// ---------------------------------------------------------------------------
extern "C" void kernel_launch(void* const* d_in, const int* in_sizes, int n_in,
                              void* d_out, int out_size) {
    const float* XP = (const float*)d_in[0];
    const float* XQ = (const float*)d_in[1];
    float* out = (float*)d_out;

    norms_kernel<<<(2 * Nn) / 8, 256>>>(XP, XQ);
    init_kernel<<<Nn / 256, 256>>>();
    gemmC_kernel<<<dim3(Nn / 64, Nn / 64), 256>>>(XP, XQ);
    scale_kernel<<<1, 1>>>();
    rescale_kernel<<<(int)(((size_t)Nn * Nn) / 8 / 256), 256>>>();

    for (int t = 0; t < 20; ++t) {
        upass_kernel<<<Nn / 8, 256>>>();
        if (t < 19) {
            vpass_kernel<false><<<dim3(NTILE, NCHUNK), 128>>>();
            vfinalize_kernel<<<Nn / 256, 256>>>();
        } else {
            vpass_kernel<true><<<dim3(NTILE, NCHUNK), 128>>>();
            rj_kernel<<<Nn / 256, 256>>>();
            result_kernel<<<1, 256>>>(out);
        }
    }
}